// round 5
// baseline (speedup 1.0000x reference)
#include <cuda_runtime.h>
#include <cuda_bf16.h>
#include <cstdint>

typedef unsigned long long ull;

#define L_SEQ 4096
#define DIM   1024
#define NHEAD 16
#define HDIM  64
#define PDIM  128
#define BATCH 4

// ================= scratch (device globals; no allocation allowed) =================
__device__ __nv_bfloat16 g_xh [(size_t)BATCH * L_SEQ * DIM];
__device__ __nv_bfloat16 g_xl [(size_t)BATCH * L_SEQ * DIM];
__device__ __nv_bfloat16 g_Wh[4][DIM * DIM];   // q,k,v,o hi
__device__ __nv_bfloat16 g_Wl[4][DIM * DIM];   // q,k,v,o lo
__device__ float g_Q [(size_t)BATCH * L_SEQ * DIM];
__device__ float g_KF[BATCH * 128 * DIM];
__device__ float g_VF[BATCH * 128 * DIM];
__device__ float g_Kp[BATCH * NHEAD * PDIM * HDIM];
__device__ float g_Vp[BATCH * NHEAD * PDIM * HDIM];
__device__ __nv_bfloat16 g_ATh[(size_t)BATCH * L_SEQ * DIM];
__device__ __nv_bfloat16 g_ATl[(size_t)BATCH * L_SEQ * DIM];

// ================= helpers =================
__device__ __forceinline__ uint32_t smem_u32(const void* p) {
    uint32_t a;
    asm("{ .reg .u64 t; cvta.to.shared.u64 t, %1; cvt.u32.u64 %0, t; }" : "=r"(a) : "l"(p));
    return a;
}
__device__ __forceinline__ uint32_t pkbf(__nv_bfloat16 a, __nv_bfloat16 b) {
    return (uint32_t)__bfloat16_as_ushort(a) | ((uint32_t)__bfloat16_as_ushort(b) << 16);
}

#define CP_ASYNC16(d, g) asm volatile("cp.async.cg.shared.global [%0], [%1], 16;\n" :: "r"(d), "l"(g) : "memory")
#define CP_COMMIT()      asm volatile("cp.async.commit_group;\n" ::: "memory")
#define CP_WAIT(n)       asm volatile("cp.async.wait_group %0;\n" :: "n"(n) : "memory")

__device__ __forceinline__ void ldsm_x4(uint32_t* r, uint32_t addr) {
    asm volatile("ldmatrix.sync.aligned.m8n8.x4.shared.b16 {%0,%1,%2,%3}, [%4];"
        : "=r"(r[0]), "=r"(r[1]), "=r"(r[2]), "=r"(r[3]) : "r"(addr));
}
__device__ __forceinline__ void mma16816(float* c, const uint32_t* a, const uint32_t* b) {
    asm volatile("mma.sync.aligned.m16n8k16.row.col.f32.bf16.bf16.f32 "
        "{%0,%1,%2,%3}, {%4,%5,%6,%7}, {%8,%9}, {%0,%1,%2,%3};"
        : "+f"(c[0]), "+f"(c[1]), "+f"(c[2]), "+f"(c[3])
        : "r"(a[0]), "r"(a[1]), "r"(a[2]), "r"(a[3]), "r"(b[0]), "r"(b[1]));
}

// ================= hi/lo bf16 split =================
__global__ void split_bf16(const float4* __restrict__ src, uint2* __restrict__ hi,
                           uint2* __restrict__ lo, int n4)
{
    int i = blockIdx.x * blockDim.x + threadIdx.x;
    if (i >= n4) return;
    float4 v = src[i];
    __nv_bfloat16 h0 = __float2bfloat16_rn(v.x), h1 = __float2bfloat16_rn(v.y);
    __nv_bfloat16 h2 = __float2bfloat16_rn(v.z), h3 = __float2bfloat16_rn(v.w);
    __nv_bfloat16 l0 = __float2bfloat16_rn(v.x - __bfloat162float(h0));
    __nv_bfloat16 l1 = __float2bfloat16_rn(v.y - __bfloat162float(h1));
    __nv_bfloat16 l2 = __float2bfloat16_rn(v.z - __bfloat162float(h2));
    __nv_bfloat16 l3 = __float2bfloat16_rn(v.w - __bfloat162float(h3));
    hi[i] = make_uint2(pkbf(h0, h1), pkbf(h2, h3));
    lo[i] = make_uint2(pkbf(l0, l1), pkbf(l2, l3));
}

// all four weight matrices in one launch: w = blockIdx.y
__global__ void split_bf16_w(const float4* __restrict__ Wq, const float4* __restrict__ Wk,
                             const float4* __restrict__ Wv, const float4* __restrict__ Wo,
                             int n4)
{
    int i = blockIdx.x * blockDim.x + threadIdx.x;
    if (i >= n4) return;
    int w = blockIdx.y;
    const float4* src = (w == 0) ? Wq : (w == 1) ? Wk : (w == 2) ? Wv : Wo;
    float4 v = src[i];
    __nv_bfloat16 h0 = __float2bfloat16_rn(v.x), h1 = __float2bfloat16_rn(v.y);
    __nv_bfloat16 h2 = __float2bfloat16_rn(v.z), h3 = __float2bfloat16_rn(v.w);
    __nv_bfloat16 l0 = __float2bfloat16_rn(v.x - __bfloat162float(h0));
    __nv_bfloat16 l1 = __float2bfloat16_rn(v.y - __bfloat162float(h1));
    __nv_bfloat16 l2 = __float2bfloat16_rn(v.z - __bfloat162float(h2));
    __nv_bfloat16 l3 = __float2bfloat16_rn(v.w - __bfloat162float(h3));
    ((uint2*)g_Wh[w])[i] = make_uint2(pkbf(h0, h1), pkbf(h2, h3));
    ((uint2*)g_Wl[w])[i] = make_uint2(pkbf(l0, l1), pkbf(l2, l3));
}

// ================= HMMA split-GEMM: C[M,N] = (Ah+Al) @ (Bh+Bl)^T (drop Al*Bl) =================
// CTA tile 128(M) x 256(N), BK=32. 8 warps: wm = wid&1 (2x M64), wn = wid>>1 (4x N64).
// smem rows of 64B, XOR swizzle on 16B chunks: c ^= (row>>1)&3.
constexpr int A_TILE_B = 128 * 64;                     // 8 KB
constexpr int B_TILE_B = 256 * 64;                     // 16 KB
constexpr int STAGE_B  = 2 * A_TILE_B + 2 * B_TILE_B;  // 48 KB: [Ah][Al][Bh][Bl]
constexpr int HM_SMEM  = 2 * STAGE_B;                  // 96 KB
constexpr int OFF_AL = A_TILE_B;
constexpr int OFF_BH = 2 * A_TILE_B;
constexpr int OFF_BL = 2 * A_TILE_B + B_TILE_B;

__device__ __forceinline__ uint32_t a_addr(uint32_t tb, int row0, int kk, int lane) {
    int row = row0 + (lane & 15);
    int c = (2 * kk + (lane >> 4)) ^ ((row >> 1) & 3);
    return tb + row * 64 + c * 16;
}
__device__ __forceinline__ uint32_t b_addr(uint32_t tb, int n0, int kk, int lane) {
    int g = lane >> 3, lr = lane & 7;
    int n = n0 + lr + (g >> 1) * 8;
    int c = (2 * kk + (g & 1)) ^ ((n >> 1) & 3);
    return tb + n * 64 + c * 16;
}

template<int GATHER>
__device__ __forceinline__ void hm_load(uint32_t stb,
    const __nv_bfloat16* Ah, const __nv_bfloat16* Al,
    const __nv_bfloat16* Bh, const __nv_bfloat16* Bl,
    int brow, int bcol, int kofs, int K, int tid)
{
    // A tiles: 128 rows x 64B = 512 chunks each
#pragma unroll
    for (int t = 0; t < 2; t++) {
        const __nv_bfloat16* src = (t == 0) ? Ah : Al;
#pragma unroll
        for (int i = 0; i < 2; i++) {
            int id = tid + i * 256;              // 0..511
            int row = id >> 2, c = id & 3;
            int gr = brow + row;
            if (GATHER) gr = (gr >> 7) * L_SEQ + (gr & 127);
            const void* g = src + (size_t)gr * K + kofs + c * 8;
            uint32_t d = stb + t * A_TILE_B + row * 64 + ((c ^ ((row >> 1) & 3)) * 16);
            CP_ASYNC16(d, g);
        }
    }
    // B tiles: 256 rows x 64B = 1024 chunks each
#pragma unroll
    for (int t = 0; t < 2; t++) {
        const __nv_bfloat16* src = (t == 0) ? Bh : Bl;
#pragma unroll
        for (int i = 0; i < 4; i++) {
            int id = tid + i * 256;              // 0..1023
            int row = id >> 2, c = id & 3;
            const void* g = src + (size_t)(bcol + row) * K + kofs + c * 8;
            uint32_t d = stb + OFF_BH + t * B_TILE_B + row * 64 + ((c ^ ((row >> 1) & 3)) * 16);
            CP_ASYNC16(d, g);
        }
    }
}

template<int ROPE, int GATHER>
__global__ __launch_bounds__(256, 1)
void hmma_gemm(const __nv_bfloat16* __restrict__ Ah, const __nv_bfloat16* __restrict__ Al,
               const __nv_bfloat16* __restrict__ Bh, const __nv_bfloat16* __restrict__ Bl,
               float* __restrict__ C, int M, int N, int K,
               const float* __restrict__ cosT, const float* __restrict__ sinT, int lmask)
{
    extern __shared__ __align__(128) char smem[];
    uint32_t sb = smem_u32(smem);
    const int tid = threadIdx.x;
    const int lane = tid & 31;
    const int wid = tid >> 5;
    const int wm = wid & 1, wn = wid >> 1;        // warp tile 64(M) x 64(N)
    const int brow = blockIdx.y * 128, bcol = blockIdx.x * 256;

    float acc[4][8][4];
#pragma unroll
    for (int a = 0; a < 4; a++)
#pragma unroll
        for (int b = 0; b < 8; b++)
#pragma unroll
            for (int c = 0; c < 4; c++) acc[a][b][c] = 0.f;

    const int NIT = K / 32;    // 32
    hm_load<GATHER>(sb, Ah, Al, Bh, Bl, brow, bcol, 0, K, tid);
    CP_COMMIT();
    hm_load<GATHER>(sb + STAGE_B, Ah, Al, Bh, Bl, brow, bcol, 32, K, tid);
    CP_COMMIT();

    for (int it = 0; it < NIT; it++) {
        int s = it & 1;
        CP_WAIT(1);
        __syncthreads();
        uint32_t stb = sb + s * STAGE_B;
#pragma unroll
        for (int kk = 0; kk < 2; kk++) {
            uint32_t af[16], bhf[16], blf[16];
#pragma unroll
            for (int mt = 0; mt < 4; mt++)
                ldsm_x4(af + mt * 4, a_addr(stb, wm * 64 + mt * 16, kk, lane));
#pragma unroll
            for (int np = 0; np < 4; np++)
                ldsm_x4(bhf + np * 4, b_addr(stb + OFF_BH, wn * 64 + np * 16, kk, lane));
#pragma unroll
            for (int np = 0; np < 4; np++)
                ldsm_x4(blf + np * 4, b_addr(stb + OFF_BL, wn * 64 + np * 16, kk, lane));
            // Ah*Bh + Ah*Bl
#pragma unroll
            for (int mt = 0; mt < 4; mt++)
#pragma unroll
                for (int nt = 0; nt < 8; nt++) {
                    const uint32_t* bp = bhf + (nt >> 1) * 4 + (nt & 1) * 2;
                    const uint32_t* lp = blf + (nt >> 1) * 4 + (nt & 1) * 2;
                    mma16816(acc[mt][nt], af + mt * 4, bp);
                    mma16816(acc[mt][nt], af + mt * 4, lp);
                }
            // reload Al over af, multiply against Bh
#pragma unroll
            for (int mt = 0; mt < 4; mt++)
                ldsm_x4(af + mt * 4, a_addr(stb + OFF_AL, wm * 64 + mt * 16, kk, lane));
#pragma unroll
            for (int mt = 0; mt < 4; mt++)
#pragma unroll
                for (int nt = 0; nt < 8; nt++)
                    mma16816(acc[mt][nt], af + mt * 4, bhf + (nt >> 1) * 4 + (nt & 1) * 2);
        }
        __syncthreads();
        if (it + 2 < NIT)
            hm_load<GATHER>(sb + s * STAGE_B, Ah, Al, Bh, Bl, brow, bcol, (it + 2) * 32, K, tid);
        CP_COMMIT();   // empty group when no load keeps wait-count arithmetic valid
    }

    // epilogue: optional RoPE, store fp32
    const int gr_ = lane >> 2, gc = (lane & 3) * 2;
#pragma unroll
    for (int mt = 0; mt < 4; mt++) {
        int r0 = brow + wm * 64 + mt * 16 + gr_;
#pragma unroll
        for (int nt = 0; nt < 8; nt++) {
            int col = bcol + wn * 64 + nt * 8 + gc;
            float c0 = acc[mt][nt][0], c1 = acc[mt][nt][1];
            float c2 = acc[mt][nt][2], c3 = acc[mt][nt][3];
            if (ROPE) {
                int f = (col & 63) >> 1;
                int l0 = r0 & lmask;
                float cc = cosT[l0 * 32 + f], ss = sinT[l0 * 32 + f];
                float t0 = c0 * cc - c1 * ss, t1 = c0 * ss + c1 * cc;
                c0 = t0; c1 = t1;
                int l1 = (r0 + 8) & lmask;
                cc = cosT[l1 * 32 + f]; ss = sinT[l1 * 32 + f];
                t0 = c2 * cc - c3 * ss; t1 = c2 * ss + c3 * cc;
                c2 = t0; c3 = t1;
            }
            *(float2*)(C + (size_t)r0 * N + col)       = make_float2(c0, c1);
            *(float2*)(C + (size_t)(r0 + 8) * N + col) = make_float2(c2, c3);
        }
    }
}

// ================= projection: Kp[b,h,p,d] = sum_{l<=p} kpm[p,l]*KF[b,l,h*64+d] =================
__global__ __launch_bounds__(256)
void proj_kernel(const float* __restrict__ Kf, const float* __restrict__ Vf,
                 const float* __restrict__ kpm, const float* __restrict__ vpm,
                 float* __restrict__ Kp, float* __restrict__ Vp)
{
    __shared__ float s[PDIM][HDIM + 4];
    const int bh = blockIdx.x;
    const int b = bh >> 4, h = bh & 15;
    const int tid = threadIdx.x;
    const int p = tid & 127;
    const int half = tid >> 7;

#pragma unroll 1
    for (int phase = 0; phase < 2; phase++) {
        const float* src = phase == 0 ? Kf : Vf;
        const float* pm  = phase == 0 ? kpm : vpm;
        float* dst_base  = phase == 0 ? Kp : Vp;

        for (int i = tid; i < PDIM * (HDIM / 4); i += 256) {
            int l = i >> 4, c4 = (i & 15) * 4;
            float4 v = *(const float4*)(src + ((size_t)(b * 128 + l)) * DIM + h * HDIM + c4);
            s[l][c4] = v.x; s[l][c4 + 1] = v.y; s[l][c4 + 2] = v.z; s[l][c4 + 3] = v.w;
        }
        __syncthreads();

        float4 acc[8];
#pragma unroll
        for (int j = 0; j < 8; j++) acc[j] = make_float4(0.f, 0.f, 0.f, 0.f);

        for (int lc = 0; lc <= p; lc++) {
            float wv = pm[(size_t)p * 4096 + lc];
#pragma unroll
            for (int j = 0; j < 8; j++) {
                float4 kv = *(const float4*)&s[lc][half * 32 + j * 4];
                acc[j].x += wv * kv.x; acc[j].y += wv * kv.y;
                acc[j].z += wv * kv.z; acc[j].w += wv * kv.w;
            }
        }
        float* dst = dst_base + ((size_t)bh * PDIM + p) * HDIM + half * 32;
#pragma unroll
        for (int j = 0; j < 8; j++) *(float4*)(dst + j * 4) = acc[j];
        __syncthreads();
    }
}

// ================= attention (verified math, bf16 hi/lo output) =================
__global__ __launch_bounds__(256, 1)
void attn_kernel(const float* __restrict__ Q, const float* __restrict__ Kp,
                 const float* __restrict__ Vp,
                 __nv_bfloat16* __restrict__ Oh, __nv_bfloat16* __restrict__ Ol)
{
    __shared__ float s[PDIM][HDIM + 4];
    const int bid = blockIdx.x;
    const int ltile = bid & 15;
    const int bh = bid >> 4;
    const int b = bh >> 4;
    const int h = bh & 15;
    const int tid = threadIdx.x;
    const int l = ltile * 256 + tid;
    const size_t qbase = ((size_t)(b * L_SEQ + l)) * DIM + h * HDIM;

    for (int i = tid; i < PDIM * (HDIM / 4); i += 256) {
        int p = i >> 4, c4 = (i & 15) * 4;
        float4 v = *(const float4*)(Kp + ((size_t)bh * PDIM + p) * HDIM + c4);
        s[p][c4] = v.x; s[p][c4 + 1] = v.y; s[p][c4 + 2] = v.z; s[p][c4 + 3] = v.w;
    }
    __syncthreads();

    float w[PDIM];
#pragma unroll
    for (int p = 0; p < PDIM; p++) w[p] = 0.f;

    for (int d4 = 0; d4 < HDIM / 4; d4++) {
        float4 q4 = *(const float4*)(Q + qbase + d4 * 4);
#pragma unroll
        for (int p = 0; p < PDIM; p++) {
            float4 k4 = *(const float4*)&s[p][d4 * 4];
            w[p] += q4.x * k4.x + q4.y * k4.y + q4.z * k4.z + q4.w * k4.w;
        }
    }

    float m = -1e30f;
#pragma unroll
    for (int p = 0; p < PDIM; p++) {
        w[p] = (p <= l) ? w[p] * 0.125f : -1e30f;
        m = fmaxf(m, w[p]);
    }
    float Z = 0.f;
#pragma unroll
    for (int p = 0; p < PDIM; p++) {
        float e = __expf(w[p] - m);
        w[p] = e;
        Z += e;
    }
    float inv = 1.0f / Z;
#pragma unroll
    for (int p = 0; p < PDIM; p++) w[p] *= inv;

    __syncthreads();
    for (int i = tid; i < PDIM * (HDIM / 4); i += 256) {
        int p = i >> 4, c4 = (i & 15) * 4;
        float4 v = *(const float4*)(Vp + ((size_t)bh * PDIM + p) * HDIM + c4);
        s[p][c4] = v.x; s[p][c4 + 1] = v.y; s[p][c4 + 2] = v.z; s[p][c4 + 3] = v.w;
    }
    __syncthreads();

    for (int d4 = 0; d4 < HDIM / 4; d4++) {
        float4 o = make_float4(0.f, 0.f, 0.f, 0.f);
#pragma unroll
        for (int p = 0; p < PDIM; p++) {
            float4 v4 = *(const float4*)&s[p][d4 * 4];
            o.x += w[p] * v4.x; o.y += w[p] * v4.y;
            o.z += w[p] * v4.z; o.w += w[p] * v4.w;
        }
        __nv_bfloat16 h0 = __float2bfloat16_rn(o.x), h1 = __float2bfloat16_rn(o.y);
        __nv_bfloat16 h2 = __float2bfloat16_rn(o.z), h3 = __float2bfloat16_rn(o.w);
        __nv_bfloat16 e0 = __float2bfloat16_rn(o.x - __bfloat162float(h0));
        __nv_bfloat16 e1 = __float2bfloat16_rn(o.y - __bfloat162float(h1));
        __nv_bfloat16 e2 = __float2bfloat16_rn(o.z - __bfloat162float(h2));
        __nv_bfloat16 e3 = __float2bfloat16_rn(o.w - __bfloat162float(h3));
        *(uint2*)(Oh + qbase + d4 * 4) = make_uint2(pkbf(h0, h1), pkbf(h2, h3));
        *(uint2*)(Ol + qbase + d4 * 4) = make_uint2(pkbf(e0, e1), pkbf(e2, e3));
    }
}

// ================= launch =================
extern "C" void kernel_launch(void* const* d_in, const int* in_sizes, int n_in,
                              void* d_out, int out_size)
{
    const float* x   = (const float*)d_in[0];
    const float* fc  = (const float*)d_in[1];
    const float* fs  = (const float*)d_in[2];
    const float* Wq  = (const float*)d_in[3];
    const float* Wk  = (const float*)d_in[4];
    const float* Wv  = (const float*)d_in[5];
    const float* Wo  = (const float*)d_in[6];
    const float* kpm = (const float*)d_in[7];
    const float* vpm = (const float*)d_in[8];
    float* out = (float*)d_out;

    static bool inited = false;
    static __nv_bfloat16 *pxh, *pxl, *pWh[4], *pWl[4], *pATh, *pATl;
    static float *pQ, *pKF, *pVF, *pKp, *pVp;
    if (!inited) {
        cudaGetSymbolAddress((void**)&pxh,  g_xh);
        cudaGetSymbolAddress((void**)&pxl,  g_xl);
        __nv_bfloat16* base_h; cudaGetSymbolAddress((void**)&base_h, g_Wh);
        __nv_bfloat16* base_l; cudaGetSymbolAddress((void**)&base_l, g_Wl);
        for (int i = 0; i < 4; i++) { pWh[i] = base_h + (size_t)i * DIM * DIM; pWl[i] = base_l + (size_t)i * DIM * DIM; }
        cudaGetSymbolAddress((void**)&pATh, g_ATh); cudaGetSymbolAddress((void**)&pATl, g_ATl);
        cudaGetSymbolAddress((void**)&pQ,  g_Q);
        cudaGetSymbolAddress((void**)&pKF, g_KF);
        cudaGetSymbolAddress((void**)&pVF, g_VF);
        cudaGetSymbolAddress((void**)&pKp, g_Kp);
        cudaGetSymbolAddress((void**)&pVp, g_Vp);
        cudaFuncSetAttribute(hmma_gemm<1,0>, cudaFuncAttributeMaxDynamicSharedMemorySize, HM_SMEM);
        cudaFuncSetAttribute(hmma_gemm<1,1>, cudaFuncAttributeMaxDynamicSharedMemorySize, HM_SMEM);
        cudaFuncSetAttribute(hmma_gemm<0,1>, cudaFuncAttributeMaxDynamicSharedMemorySize, HM_SMEM);
        cudaFuncSetAttribute(hmma_gemm<0,0>, cudaFuncAttributeMaxDynamicSharedMemorySize, HM_SMEM);
        inited = true;
    }

    const int Mq = BATCH * L_SEQ;                    // 16384
    const int n4x = (int)((size_t)Mq * DIM / 4);
    const int n4w = DIM * DIM / 4;

    split_bf16<<<n4x / 256, 256>>>((const float4*)x,  (uint2*)pxh,  (uint2*)pxl,  n4x);
    split_bf16_w<<<dim3(n4w / 256, 4), 256>>>((const float4*)Wq, (const float4*)Wk,
                                              (const float4*)Wv, (const float4*)Wo, n4w);

    // Q = rope(x @ Wq^T)  [16384, 1024]
    hmma_gemm<1,0><<<dim3(DIM / 256, Mq / 128), 256, HM_SMEM>>>(
        pxh, pxl, pWh[0], pWl[0], pQ, Mq, DIM, DIM, fc, fs, L_SEQ - 1);
    // K first-128 = rope(x128 @ Wk^T)  [512, 1024]
    hmma_gemm<1,1><<<dim3(DIM / 256, (BATCH * 128) / 128), 256, HM_SMEM>>>(
        pxh, pxl, pWh[1], pWl[1], pKF, BATCH * 128, DIM, DIM, fc, fs, 127);
    // V first-128 = x128 @ Wv^T
    hmma_gemm<0,1><<<dim3(DIM / 256, (BATCH * 128) / 128), 256, HM_SMEM>>>(
        pxh, pxl, pWh[2], pWl[2], pVF, BATCH * 128, DIM, DIM, nullptr, nullptr, 0);
    // causal low-rank projections
    proj_kernel<<<BATCH * NHEAD, 256>>>(pKF, pVF, kpm, vpm, pKp, pVp);
    // attention -> bf16 hi/lo
    attn_kernel<<<BATCH * NHEAD * (L_SEQ / 256), 256>>>(pQ, pKp, pVp, pATh, pATl);
    // out = attn @ Wo^T
    hmma_gemm<0,0><<<dim3(DIM / 256, Mq / 128), 256, HM_SMEM>>>(
        pATh, pATl, pWh[3], pWl[3], out, Mq, DIM, DIM, nullptr, nullptr, 0);
}

// round 6
// speedup vs baseline: 1.2523x; 1.2523x over previous
#include <cuda_runtime.h>
#include <cuda_bf16.h>
#include <cstdint>

typedef unsigned long long ull;

#define L_SEQ 4096
#define DIM   1024
#define NHEAD 16
#define HDIM  64
#define PDIM  128
#define BATCH 4

// ================= scratch (device globals; no allocation allowed) =================
__device__ __nv_bfloat16 g_xh [(size_t)BATCH * L_SEQ * DIM];
__device__ __nv_bfloat16 g_xl [(size_t)BATCH * L_SEQ * DIM];
__device__ __nv_bfloat16 g_Wh[4][DIM * DIM];   // q,k,v,o hi
__device__ __nv_bfloat16 g_Wl[4][DIM * DIM];   // q,k,v,o lo
__device__ float g_Q [(size_t)BATCH * L_SEQ * DIM];
__device__ float g_KF[BATCH * 128 * DIM];
__device__ float g_VF[BATCH * 128 * DIM];
__device__ float g_Kp[BATCH * NHEAD * PDIM * HDIM];
__device__ float g_Vp[BATCH * NHEAD * PDIM * HDIM];
__device__ __nv_bfloat16 g_ATh[(size_t)BATCH * L_SEQ * DIM];
__device__ __nv_bfloat16 g_ATl[(size_t)BATCH * L_SEQ * DIM];

// ================= helpers =================
__device__ __forceinline__ uint32_t smem_u32(const void* p) {
    uint32_t a;
    asm("{ .reg .u64 t; cvta.to.shared.u64 t, %1; cvt.u32.u64 %0, t; }" : "=r"(a) : "l"(p));
    return a;
}
__device__ __forceinline__ uint32_t pkbf(__nv_bfloat16 a, __nv_bfloat16 b) {
    return (uint32_t)__bfloat16_as_ushort(a) | ((uint32_t)__bfloat16_as_ushort(b) << 16);
}

#define CP_ASYNC16(d, g) asm volatile("cp.async.cg.shared.global [%0], [%1], 16;\n" :: "r"(d), "l"(g) : "memory")
#define CP_COMMIT()      asm volatile("cp.async.commit_group;\n" ::: "memory")
#define CP_WAIT(n)       asm volatile("cp.async.wait_group %0;\n" :: "n"(n) : "memory")

__device__ __forceinline__ void ldsm_x4(uint32_t* r, uint32_t addr) {
    asm volatile("ldmatrix.sync.aligned.m8n8.x4.shared.b16 {%0,%1,%2,%3}, [%4];"
        : "=r"(r[0]), "=r"(r[1]), "=r"(r[2]), "=r"(r[3]) : "r"(addr));
}
__device__ __forceinline__ void mma16816(float* c, const uint32_t* a, const uint32_t* b) {
    asm volatile("mma.sync.aligned.m16n8k16.row.col.f32.bf16.bf16.f32 "
        "{%0,%1,%2,%3}, {%4,%5,%6,%7}, {%8,%9}, {%0,%1,%2,%3};"
        : "+f"(c[0]), "+f"(c[1]), "+f"(c[2]), "+f"(c[3])
        : "r"(a[0]), "r"(a[1]), "r"(a[2]), "r"(a[3]), "r"(b[0]), "r"(b[1]));
}

// ================= hi/lo bf16 split =================
__global__ void split_bf16(const float4* __restrict__ src, uint2* __restrict__ hi,
                           uint2* __restrict__ lo, int n4)
{
    int i = blockIdx.x * blockDim.x + threadIdx.x;
    if (i >= n4) return;
    float4 v = src[i];
    __nv_bfloat16 h0 = __float2bfloat16_rn(v.x), h1 = __float2bfloat16_rn(v.y);
    __nv_bfloat16 h2 = __float2bfloat16_rn(v.z), h3 = __float2bfloat16_rn(v.w);
    __nv_bfloat16 l0 = __float2bfloat16_rn(v.x - __bfloat162float(h0));
    __nv_bfloat16 l1 = __float2bfloat16_rn(v.y - __bfloat162float(h1));
    __nv_bfloat16 l2 = __float2bfloat16_rn(v.z - __bfloat162float(h2));
    __nv_bfloat16 l3 = __float2bfloat16_rn(v.w - __bfloat162float(h3));
    hi[i] = make_uint2(pkbf(h0, h1), pkbf(h2, h3));
    lo[i] = make_uint2(pkbf(l0, l1), pkbf(l2, l3));
}

// all four weight matrices in one launch: w = blockIdx.y
__global__ void split_bf16_w(const float4* __restrict__ Wq, const float4* __restrict__ Wk,
                             const float4* __restrict__ Wv, const float4* __restrict__ Wo,
                             int n4)
{
    int i = blockIdx.x * blockDim.x + threadIdx.x;
    if (i >= n4) return;
    int w = blockIdx.y;
    const float4* src = (w == 0) ? Wq : (w == 1) ? Wk : (w == 2) ? Wv : Wo;
    float4 v = src[i];
    __nv_bfloat16 h0 = __float2bfloat16_rn(v.x), h1 = __float2bfloat16_rn(v.y);
    __nv_bfloat16 h2 = __float2bfloat16_rn(v.z), h3 = __float2bfloat16_rn(v.w);
    __nv_bfloat16 l0 = __float2bfloat16_rn(v.x - __bfloat162float(h0));
    __nv_bfloat16 l1 = __float2bfloat16_rn(v.y - __bfloat162float(h1));
    __nv_bfloat16 l2 = __float2bfloat16_rn(v.z - __bfloat162float(h2));
    __nv_bfloat16 l3 = __float2bfloat16_rn(v.w - __bfloat162float(h3));
    ((uint2*)g_Wh[w])[i] = make_uint2(pkbf(h0, h1), pkbf(h2, h3));
    ((uint2*)g_Wl[w])[i] = make_uint2(pkbf(l0, l1), pkbf(l2, l3));
}

// ================= HMMA split-GEMM core (round-4 verified config) =================
// CTA tile 128x128, BK=32. 8 warps: wm = wid&1 (2x M64), wn = wid>>1 (4x N32).
// smem tiles 128 rows x 64B, XOR swizzle on 16B chunks: c ^= (row>>1)&3.
constexpr int TILE_BYTES  = 128 * 64;          // 8 KB
constexpr int STAGE_BYTES = 4 * TILE_BYTES;    // Ah, Al, Bh, Bl
constexpr int HM_SMEM     = 2 * STAGE_BYTES;   // 64 KB

__device__ __forceinline__ uint32_t a_addr(uint32_t tb, int row0, int kk, int lane) {
    int row = row0 + (lane & 15);
    int c = (2 * kk + (lane >> 4)) ^ ((row >> 1) & 3);
    return tb + row * 64 + c * 16;
}
__device__ __forceinline__ uint32_t b_addr(uint32_t tb, int n0, int kk, int lane) {
    int g = lane >> 3, lr = lane & 7;
    int n = n0 + lr + (g >> 1) * 8;
    int c = (2 * kk + (g & 1)) ^ ((n >> 1) & 3);
    return tb + n * 64 + c * 16;
}

__device__ __forceinline__ void hm_load(uint32_t stb,
    const __nv_bfloat16* Ah, const __nv_bfloat16* Al,
    const __nv_bfloat16* Bh, const __nv_bfloat16* Bl,
    int brow, int bcol, int kofs, int K, int tid, bool gather)
{
#pragma unroll
    for (int t = 0; t < 4; t++) {
        const __nv_bfloat16* src = (t == 0) ? Ah : (t == 1) ? Al : (t == 2) ? Bh : Bl;
        int r0 = (t < 2) ? brow : bcol;
#pragma unroll
        for (int i = 0; i < 2; i++) {
            int id = tid + i * 256;          // 0..511
            int row = id >> 2, c = id & 3;
            int gr = r0 + row;
            if (gather && t < 2) gr = (gr >> 7) * L_SEQ + (gr & 127);
            const void* g = src + (size_t)gr * K + kofs + c * 8;
            uint32_t d = stb + t * TILE_BYTES + row * 64 + ((c ^ ((row >> 1) & 3)) * 16);
            CP_ASYNC16(d, g);
        }
    }
}

// body shared by both GEMM kernels; rope/gather are CTA-uniform runtime flags
__device__ __forceinline__ void hm_body(
    const __nv_bfloat16* Ah, const __nv_bfloat16* Al,
    const __nv_bfloat16* Bh, const __nv_bfloat16* Bl,
    float* C, int brow, int bcol, int K, int N,
    const float* cosT, const float* sinT, int lmask, bool rope, bool gather,
    char* smem)
{
    uint32_t sb = smem_u32(smem);
    const int tid = threadIdx.x;
    const int lane = tid & 31;
    const int wid = tid >> 5;
    const int wm = wid & 1, wn = wid >> 1;

    float acc[4][4][4];
#pragma unroll
    for (int a = 0; a < 4; a++)
#pragma unroll
        for (int b = 0; b < 4; b++)
#pragma unroll
            for (int c = 0; c < 4; c++) acc[a][b][c] = 0.f;

    const int NIT = K / 32;    // 32
    hm_load(sb, Ah, Al, Bh, Bl, brow, bcol, 0, K, tid, gather);
    CP_COMMIT();
    hm_load(sb + STAGE_BYTES, Ah, Al, Bh, Bl, brow, bcol, 32, K, tid, gather);
    CP_COMMIT();

    for (int it = 0; it < NIT; it++) {
        int s = it & 1;
        CP_WAIT(1);
        __syncthreads();
        uint32_t stb = sb + s * STAGE_BYTES;
#pragma unroll
        for (int kk = 0; kk < 2; kk++) {
            uint32_t af[16], bhf[8], blf[8];
#pragma unroll
            for (int mt = 0; mt < 4; mt++)
                ldsm_x4(af + mt * 4, a_addr(stb, wm * 64 + mt * 16, kk, lane));
#pragma unroll
            for (int np = 0; np < 2; np++)
                ldsm_x4(bhf + np * 4, b_addr(stb + 2 * TILE_BYTES, wn * 32 + np * 16, kk, lane));
#pragma unroll
            for (int np = 0; np < 2; np++)
                ldsm_x4(blf + np * 4, b_addr(stb + 3 * TILE_BYTES, wn * 32 + np * 16, kk, lane));
#pragma unroll
            for (int mt = 0; mt < 4; mt++)
#pragma unroll
                for (int nt = 0; nt < 4; nt++) {
                    const uint32_t* bp = bhf + (nt >> 1) * 4 + (nt & 1) * 2;
                    const uint32_t* lp = blf + (nt >> 1) * 4 + (nt & 1) * 2;
                    mma16816(acc[mt][nt], af + mt * 4, bp);
                    mma16816(acc[mt][nt], af + mt * 4, lp);
                }
            // reload Al over af, multiply against Bh
#pragma unroll
            for (int mt = 0; mt < 4; mt++)
                ldsm_x4(af + mt * 4, a_addr(stb + TILE_BYTES, wm * 64 + mt * 16, kk, lane));
#pragma unroll
            for (int mt = 0; mt < 4; mt++)
#pragma unroll
                for (int nt = 0; nt < 4; nt++)
                    mma16816(acc[mt][nt], af + mt * 4, bhf + (nt >> 1) * 4 + (nt & 1) * 2);
        }
        __syncthreads();
        if (it + 2 < NIT)
            hm_load(sb + s * STAGE_BYTES, Ah, Al, Bh, Bl, brow, bcol, (it + 2) * 32, K, tid, gather);
        CP_COMMIT();
    }

    // epilogue: optional RoPE, store fp32
    const int gr_ = lane >> 2, gc = (lane & 3) * 2;
#pragma unroll
    for (int mt = 0; mt < 4; mt++) {
        int r0 = brow + wm * 64 + mt * 16 + gr_;
#pragma unroll
        for (int nt = 0; nt < 4; nt++) {
            int col = bcol + wn * 32 + nt * 8 + gc;
            float c0 = acc[mt][nt][0], c1 = acc[mt][nt][1];
            float c2 = acc[mt][nt][2], c3 = acc[mt][nt][3];
            if (rope) {
                int f = (col & 63) >> 1;
                int l0 = r0 & lmask;
                float cc = cosT[l0 * 32 + f], ss = sinT[l0 * 32 + f];
                float t0 = c0 * cc - c1 * ss, t1 = c0 * ss + c1 * cc;
                c0 = t0; c1 = t1;
                int l1 = (r0 + 8) & lmask;
                cc = cosT[l1 * 32 + f]; ss = sinT[l1 * 32 + f];
                t0 = c2 * cc - c3 * ss; t1 = c2 * ss + c3 * cc;
                c2 = t0; c3 = t1;
            }
            *(float2*)(C + (size_t)r0 * N + col)       = make_float2(c0, c1);
            *(float2*)(C + (size_t)(r0 + 8) * N + col) = make_float2(c2, c3);
        }
    }
}

// fused Q/K/V projection GEMM: grid (8, 136)
//   y <  128      -> Q tile: rope, no gather, lmask=4095
//   y in [128,132) -> K tile: rope, gather, lmask=127
//   y in [132,136) -> V tile: no rope, gather
__global__ __launch_bounds__(256, 2)
void qkv_gemm(const __nv_bfloat16* __restrict__ xh, const __nv_bfloat16* __restrict__ xl,
              const __nv_bfloat16* __restrict__ Wqh, const __nv_bfloat16* __restrict__ Wql,
              const __nv_bfloat16* __restrict__ Wkh, const __nv_bfloat16* __restrict__ Wkl,
              const __nv_bfloat16* __restrict__ Wvh, const __nv_bfloat16* __restrict__ Wvl,
              float* __restrict__ Q, float* __restrict__ KF, float* __restrict__ VF,
              const float* __restrict__ cosT, const float* __restrict__ sinT)
{
    extern __shared__ __align__(128) char smem[];
    const int y = blockIdx.y;
    const int bcol = blockIdx.x * 128;

    const __nv_bfloat16 *Bh, *Bl;
    float* C;
    int brow, lmask;
    bool rope, gather;
    if (y < 128)      { Bh = Wqh; Bl = Wql; C = Q;  brow = y * 128;         rope = true;  gather = false; lmask = L_SEQ - 1; }
    else if (y < 132) { Bh = Wkh; Bl = Wkl; C = KF; brow = (y - 128) * 128; rope = true;  gather = true;  lmask = 127; }
    else              { Bh = Wvh; Bl = Wvl; C = VF; brow = (y - 132) * 128; rope = false; gather = true;  lmask = 0; }

    hm_body(xh, xl, Bh, Bl, C, brow, bcol, DIM, DIM, cosT, sinT, lmask, rope, gather, smem);
}

// plain output GEMM: out = AT @ Wo^T
__global__ __launch_bounds__(256, 2)
void o_gemm(const __nv_bfloat16* __restrict__ Ah, const __nv_bfloat16* __restrict__ Al,
            const __nv_bfloat16* __restrict__ Bh, const __nv_bfloat16* __restrict__ Bl,
            float* __restrict__ C)
{
    extern __shared__ __align__(128) char smem[];
    hm_body(Ah, Al, Bh, Bl, C, blockIdx.y * 128, blockIdx.x * 128, DIM, DIM,
            nullptr, nullptr, 0, false, false, smem);
}

// ================= projection: Kp[b,h,p,d] = sum_{l<=p} kpm[p,l]*KF[b,l,h*64+d] =================
__global__ __launch_bounds__(256)
void proj_kernel(const float* __restrict__ Kf, const float* __restrict__ Vf,
                 const float* __restrict__ kpm, const float* __restrict__ vpm,
                 float* __restrict__ Kp, float* __restrict__ Vp)
{
    __shared__ float s[PDIM][HDIM + 4];
    const int bh = blockIdx.x;
    const int b = bh >> 4, h = bh & 15;
    const int tid = threadIdx.x;
    const int p = tid & 127;
    const int half = tid >> 7;

#pragma unroll 1
    for (int phase = 0; phase < 2; phase++) {
        const float* src = phase == 0 ? Kf : Vf;
        const float* pm  = phase == 0 ? kpm : vpm;
        float* dst_base  = phase == 0 ? Kp : Vp;

        for (int i = tid; i < PDIM * (HDIM / 4); i += 256) {
            int l = i >> 4, c4 = (i & 15) * 4;
            float4 v = *(const float4*)(src + ((size_t)(b * 128 + l)) * DIM + h * HDIM + c4);
            s[l][c4] = v.x; s[l][c4 + 1] = v.y; s[l][c4 + 2] = v.z; s[l][c4 + 3] = v.w;
        }
        __syncthreads();

        float4 acc[8];
#pragma unroll
        for (int j = 0; j < 8; j++) acc[j] = make_float4(0.f, 0.f, 0.f, 0.f);

        for (int lc = 0; lc <= p; lc++) {
            float wv = pm[(size_t)p * 4096 + lc];
#pragma unroll
            for (int j = 0; j < 8; j++) {
                float4 kv = *(const float4*)&s[lc][half * 32 + j * 4];
                acc[j].x += wv * kv.x; acc[j].y += wv * kv.y;
                acc[j].z += wv * kv.z; acc[j].w += wv * kv.w;
            }
        }
        float* dst = dst_base + ((size_t)bh * PDIM + p) * HDIM + half * 32;
#pragma unroll
        for (int j = 0; j < 8; j++) *(float4*)(dst + j * 4) = acc[j];
        __syncthreads();
    }
}

// ================= attention (verified math, bf16 hi/lo output) =================
__global__ __launch_bounds__(256, 1)
void attn_kernel(const float* __restrict__ Q, const float* __restrict__ Kp,
                 const float* __restrict__ Vp,
                 __nv_bfloat16* __restrict__ Oh, __nv_bfloat16* __restrict__ Ol)
{
    __shared__ float s[PDIM][HDIM + 4];
    const int bid = blockIdx.x;
    const int ltile = bid & 15;
    const int bh = bid >> 4;
    const int b = bh >> 4;
    const int h = bh & 15;
    const int tid = threadIdx.x;
    const int l = ltile * 256 + tid;
    const size_t qbase = ((size_t)(b * L_SEQ + l)) * DIM + h * HDIM;

    for (int i = tid; i < PDIM * (HDIM / 4); i += 256) {
        int p = i >> 4, c4 = (i & 15) * 4;
        float4 v = *(const float4*)(Kp + ((size_t)bh * PDIM + p) * HDIM + c4);
        s[p][c4] = v.x; s[p][c4 + 1] = v.y; s[p][c4 + 2] = v.z; s[p][c4 + 3] = v.w;
    }
    __syncthreads();

    float w[PDIM];
#pragma unroll
    for (int p = 0; p < PDIM; p++) w[p] = 0.f;

    for (int d4 = 0; d4 < HDIM / 4; d4++) {
        float4 q4 = *(const float4*)(Q + qbase + d4 * 4);
#pragma unroll
        for (int p = 0; p < PDIM; p++) {
            float4 k4 = *(const float4*)&s[p][d4 * 4];
            w[p] += q4.x * k4.x + q4.y * k4.y + q4.z * k4.z + q4.w * k4.w;
        }
    }

    float m = -1e30f;
#pragma unroll
    for (int p = 0; p < PDIM; p++) {
        w[p] = (p <= l) ? w[p] * 0.125f : -1e30f;
        m = fmaxf(m, w[p]);
    }
    float Z = 0.f;
#pragma unroll
    for (int p = 0; p < PDIM; p++) {
        float e = __expf(w[p] - m);
        w[p] = e;
        Z += e;
    }
    float inv = 1.0f / Z;
#pragma unroll
    for (int p = 0; p < PDIM; p++) w[p] *= inv;

    __syncthreads();
    for (int i = tid; i < PDIM * (HDIM / 4); i += 256) {
        int p = i >> 4, c4 = (i & 15) * 4;
        float4 v = *(const float4*)(Vp + ((size_t)bh * PDIM + p) * HDIM + c4);
        s[p][c4] = v.x; s[p][c4 + 1] = v.y; s[p][c4 + 2] = v.z; s[p][c4 + 3] = v.w;
    }
    __syncthreads();

    for (int d4 = 0; d4 < HDIM / 4; d4++) {
        float4 o = make_float4(0.f, 0.f, 0.f, 0.f);
#pragma unroll
        for (int p = 0; p < PDIM; p++) {
            float4 v4 = *(const float4*)&s[p][d4 * 4];
            o.x += w[p] * v4.x; o.y += w[p] * v4.y;
            o.z += w[p] * v4.z; o.w += w[p] * v4.w;
        }
        __nv_bfloat16 h0 = __float2bfloat16_rn(o.x), h1 = __float2bfloat16_rn(o.y);
        __nv_bfloat16 h2 = __float2bfloat16_rn(o.z), h3 = __float2bfloat16_rn(o.w);
        __nv_bfloat16 e0 = __float2bfloat16_rn(o.x - __bfloat162float(h0));
        __nv_bfloat16 e1 = __float2bfloat16_rn(o.y - __bfloat162float(h1));
        __nv_bfloat16 e2 = __float2bfloat16_rn(o.z - __bfloat162float(h2));
        __nv_bfloat16 e3 = __float2bfloat16_rn(o.w - __bfloat162float(h3));
        *(uint2*)(Oh + qbase + d4 * 4) = make_uint2(pkbf(h0, h1), pkbf(h2, h3));
        *(uint2*)(Ol + qbase + d4 * 4) = make_uint2(pkbf(e0, e1), pkbf(e2, e3));
    }
}

// ================= launch =================
extern "C" void kernel_launch(void* const* d_in, const int* in_sizes, int n_in,
                              void* d_out, int out_size)
{
    const float* x   = (const float*)d_in[0];
    const float* fc  = (const float*)d_in[1];
    const float* fs  = (const float*)d_in[2];
    const float* Wq  = (const float*)d_in[3];
    const float* Wk  = (const float*)d_in[4];
    const float* Wv  = (const float*)d_in[5];
    const float* Wo  = (const float*)d_in[6];
    const float* kpm = (const float*)d_in[7];
    const float* vpm = (const float*)d_in[8];
    float* out = (float*)d_out;

    static bool inited = false;
    static __nv_bfloat16 *pxh, *pxl, *pWh[4], *pWl[4], *pATh, *pATl;
    static float *pQ, *pKF, *pVF, *pKp, *pVp;
    if (!inited) {
        cudaGetSymbolAddress((void**)&pxh,  g_xh);
        cudaGetSymbolAddress((void**)&pxl,  g_xl);
        __nv_bfloat16* base_h; cudaGetSymbolAddress((void**)&base_h, g_Wh);
        __nv_bfloat16* base_l; cudaGetSymbolAddress((void**)&base_l, g_Wl);
        for (int i = 0; i < 4; i++) { pWh[i] = base_h + (size_t)i * DIM * DIM; pWl[i] = base_l + (size_t)i * DIM * DIM; }
        cudaGetSymbolAddress((void**)&pATh, g_ATh); cudaGetSymbolAddress((void**)&pATl, g_ATl);
        cudaGetSymbolAddress((void**)&pQ,  g_Q);
        cudaGetSymbolAddress((void**)&pKF, g_KF);
        cudaGetSymbolAddress((void**)&pVF, g_VF);
        cudaGetSymbolAddress((void**)&pKp, g_Kp);
        cudaGetSymbolAddress((void**)&pVp, g_Vp);
        cudaFuncSetAttribute(qkv_gemm, cudaFuncAttributeMaxDynamicSharedMemorySize, HM_SMEM);
        cudaFuncSetAttribute(o_gemm,   cudaFuncAttributeMaxDynamicSharedMemorySize, HM_SMEM);
        inited = true;
    }

    const int Mq = BATCH * L_SEQ;                    // 16384
    const int n4x = (int)((size_t)Mq * DIM / 4);
    const int n4w = DIM * DIM / 4;

    split_bf16<<<n4x / 256, 256>>>((const float4*)x,  (uint2*)pxh,  (uint2*)pxl,  n4x);
    split_bf16_w<<<dim3(n4w / 256, 4), 256>>>((const float4*)Wq, (const float4*)Wk,
                                              (const float4*)Wv, (const float4*)Wo, n4w);

    // fused Q + K(first-128) + V(first-128) projection GEMMs (one launch)
    qkv_gemm<<<dim3(DIM / 128, Mq / 128 + 8), 256, HM_SMEM>>>(
        pxh, pxl, pWh[0], pWl[0], pWh[1], pWl[1], pWh[2], pWl[2],
        pQ, pKF, pVF, fc, fs);
    // causal low-rank projections
    proj_kernel<<<BATCH * NHEAD, 256>>>(pKF, pVF, kpm, vpm, pKp, pVp);
    // attention -> bf16 hi/lo
    attn_kernel<<<BATCH * NHEAD * (L_SEQ / 256), 256>>>(pQ, pKp, pVp, pATh, pATl);
    // out = attn @ Wo^T
    o_gemm<<<dim3(DIM / 128, Mq / 128), 256, HM_SMEM>>>(
        pATh, pATl, pWh[3], pWl[3], out);
}

// round 7
// speedup vs baseline: 1.5256x; 1.2182x over previous
#include <cuda_runtime.h>
#include <cuda_fp16.h>
#include <cstdint>

#define L_SEQ 4096
#define DIM   1024
#define NHEAD 16
#define HDIM  64
#define PDIM  128
#define BATCH 4

// ================= scratch (device globals; no allocation allowed) =================
__device__ __half g_xh [(size_t)BATCH * L_SEQ * DIM];
__device__ __half g_xl [(size_t)BATCH * L_SEQ * DIM];
__device__ __half g_Wf[4][DIM * DIM];                 // q,k,v,o single fp16
__device__ float g_Q [(size_t)BATCH * L_SEQ * DIM];
__device__ float g_KF[BATCH * 128 * DIM];
__device__ float g_VF[BATCH * 128 * DIM];
__device__ float g_Kp[BATCH * NHEAD * PDIM * HDIM];
__device__ float g_Vp[BATCH * NHEAD * PDIM * HDIM];
__device__ __half g_ATh[(size_t)BATCH * L_SEQ * DIM];
__device__ __half g_ATl[(size_t)BATCH * L_SEQ * DIM];

// ================= helpers =================
__device__ __forceinline__ uint32_t smem_u32(const void* p) {
    uint32_t a;
    asm("{ .reg .u64 t; cvta.to.shared.u64 t, %1; cvt.u32.u64 %0, t; }" : "=r"(a) : "l"(p));
    return a;
}
__device__ __forceinline__ uint32_t pkhf(__half a, __half b) {
    return (uint32_t)__half_as_ushort(a) | ((uint32_t)__half_as_ushort(b) << 16);
}

#define CP_ASYNC16(d, g) asm volatile("cp.async.cg.shared.global [%0], [%1], 16;\n" :: "r"(d), "l"(g) : "memory")
#define CP_COMMIT()      asm volatile("cp.async.commit_group;\n" ::: "memory")
#define CP_WAIT(n)       asm volatile("cp.async.wait_group %0;\n" :: "n"(n) : "memory")

__device__ __forceinline__ void ldsm_x4(uint32_t* r, uint32_t addr) {
    asm volatile("ldmatrix.sync.aligned.m8n8.x4.shared.b16 {%0,%1,%2,%3}, [%4];"
        : "=r"(r[0]), "=r"(r[1]), "=r"(r[2]), "=r"(r[3]) : "r"(addr));
}
__device__ __forceinline__ void mma16816(float* c, const uint32_t* a, const uint32_t* b) {
    asm volatile("mma.sync.aligned.m16n8k16.row.col.f32.f16.f16.f32 "
        "{%0,%1,%2,%3}, {%4,%5,%6,%7}, {%8,%9}, {%0,%1,%2,%3};"
        : "+f"(c[0]), "+f"(c[1]), "+f"(c[2]), "+f"(c[3])
        : "r"(a[0]), "r"(a[1]), "r"(a[2]), "r"(a[3]), "r"(b[0]), "r"(b[1]));
}

// ================= fp16 splits =================
__global__ void split_fp16(const float4* __restrict__ src, uint2* __restrict__ hi,
                           uint2* __restrict__ lo, int n4)
{
    int i = blockIdx.x * blockDim.x + threadIdx.x;
    if (i >= n4) return;
    float4 v = src[i];
    __half h0 = __float2half_rn(v.x), h1 = __float2half_rn(v.y);
    __half h2 = __float2half_rn(v.z), h3 = __float2half_rn(v.w);
    __half l0 = __float2half_rn(v.x - __half2float(h0));
    __half l1 = __float2half_rn(v.y - __half2float(h1));
    __half l2 = __float2half_rn(v.z - __half2float(h2));
    __half l3 = __float2half_rn(v.w - __half2float(h3));
    hi[i] = make_uint2(pkhf(h0, h1), pkhf(h2, h3));
    lo[i] = make_uint2(pkhf(l0, l1), pkhf(l2, l3));
}

// weights: single fp16, all four matrices in one launch (w = blockIdx.y)
__global__ void split_fp16_w(const float4* __restrict__ Wq, const float4* __restrict__ Wk,
                             const float4* __restrict__ Wv, const float4* __restrict__ Wo,
                             int n4)
{
    int i = blockIdx.x * blockDim.x + threadIdx.x;
    if (i >= n4) return;
    int w = blockIdx.y;
    const float4* src = (w == 0) ? Wq : (w == 1) ? Wk : (w == 2) ? Wv : Wo;
    float4 v = src[i];
    ((uint2*)g_Wf[w])[i] = make_uint2(
        pkhf(__float2half_rn(v.x), __float2half_rn(v.y)),
        pkhf(__float2half_rn(v.z), __float2half_rn(v.w)));
}

// ================= HMMA 2-pass fp16 GEMM: C[M,N] = (Ah+Al)[M,K] @ Bh[N,K]^T =================
// CTA tile 128x128, BK=32. 8 warps: wm = wid&1 (2x M64), wn = wid>>1 (4x N32).
// smem tiles 128 rows x 64B, XOR swizzle on 16B chunks: c ^= (row>>1)&3.
constexpr int TILE_BYTES  = 128 * 64;          // 8 KB
constexpr int STAGE_BYTES = 3 * TILE_BYTES;    // Ah, Al, Bh
constexpr int HM_SMEM     = 2 * STAGE_BYTES;   // 48 KB
constexpr int OFF_AL = TILE_BYTES;
constexpr int OFF_B  = 2 * TILE_BYTES;

__device__ __forceinline__ uint32_t a_addr(uint32_t tb, int row0, int kk, int lane) {
    int row = row0 + (lane & 15);
    int c = (2 * kk + (lane >> 4)) ^ ((row >> 1) & 3);
    return tb + row * 64 + c * 16;
}
__device__ __forceinline__ uint32_t b_addr(uint32_t tb, int n0, int kk, int lane) {
    int g = lane >> 3, lr = lane & 7;
    int n = n0 + lr + (g >> 1) * 8;
    int c = (2 * kk + (g & 1)) ^ ((n >> 1) & 3);
    return tb + n * 64 + c * 16;
}

__device__ __forceinline__ void hm_load(uint32_t stb,
    const __half* Ah, const __half* Al, const __half* Bh,
    int brow, int bcol, int kofs, int K, int tid, bool gather)
{
#pragma unroll
    for (int t = 0; t < 3; t++) {
        const __half* src = (t == 0) ? Ah : (t == 1) ? Al : Bh;
        int r0 = (t < 2) ? brow : bcol;
#pragma unroll
        for (int i = 0; i < 2; i++) {
            int id = tid + i * 256;          // 0..511
            int row = id >> 2, c = id & 3;
            int gr = r0 + row;
            if (gather && t < 2) gr = (gr >> 7) * L_SEQ + (gr & 127);
            const void* g = src + (size_t)gr * K + kofs + c * 8;
            uint32_t d = stb + t * TILE_BYTES + row * 64 + ((c ^ ((row >> 1) & 3)) * 16);
            CP_ASYNC16(d, g);
        }
    }
}

// shared GEMM body; rope/gather are CTA-uniform runtime flags
__device__ __forceinline__ void hm_body(
    const __half* Ah, const __half* Al, const __half* Bh,
    float* C, int brow, int bcol, int K, int N,
    const float* cosT, const float* sinT, int lmask, bool rope, bool gather,
    char* smem)
{
    uint32_t sb = smem_u32(smem);
    const int tid = threadIdx.x;
    const int lane = tid & 31;
    const int wid = tid >> 5;
    const int wm = wid & 1, wn = wid >> 1;

    float acc[4][4][4];
#pragma unroll
    for (int a = 0; a < 4; a++)
#pragma unroll
        for (int b = 0; b < 4; b++)
#pragma unroll
            for (int c = 0; c < 4; c++) acc[a][b][c] = 0.f;

    const int NIT = K / 32;    // 32
    hm_load(sb, Ah, Al, Bh, brow, bcol, 0, K, tid, gather);
    CP_COMMIT();
    hm_load(sb + STAGE_BYTES, Ah, Al, Bh, brow, bcol, 32, K, tid, gather);
    CP_COMMIT();

    for (int it = 0; it < NIT; it++) {
        int s = it & 1;
        CP_WAIT(1);
        __syncthreads();
        uint32_t stb = sb + s * STAGE_BYTES;
#pragma unroll
        for (int kk = 0; kk < 2; kk++) {
            uint32_t af[16], bf[8];
#pragma unroll
            for (int mt = 0; mt < 4; mt++)
                ldsm_x4(af + mt * 4, a_addr(stb, wm * 64 + mt * 16, kk, lane));
#pragma unroll
            for (int np = 0; np < 2; np++)
                ldsm_x4(bf + np * 4, b_addr(stb + OFF_B, wn * 32 + np * 16, kk, lane));
            // Ah * B
#pragma unroll
            for (int mt = 0; mt < 4; mt++)
#pragma unroll
                for (int nt = 0; nt < 4; nt++)
                    mma16816(acc[mt][nt], af + mt * 4, bf + (nt >> 1) * 4 + (nt & 1) * 2);
            // reload Al over af, multiply against B
#pragma unroll
            for (int mt = 0; mt < 4; mt++)
                ldsm_x4(af + mt * 4, a_addr(stb + OFF_AL, wm * 64 + mt * 16, kk, lane));
#pragma unroll
            for (int mt = 0; mt < 4; mt++)
#pragma unroll
                for (int nt = 0; nt < 4; nt++)
                    mma16816(acc[mt][nt], af + mt * 4, bf + (nt >> 1) * 4 + (nt & 1) * 2);
        }
        __syncthreads();
        if (it + 2 < NIT)
            hm_load(sb + s * STAGE_BYTES, Ah, Al, Bh, brow, bcol, (it + 2) * 32, K, tid, gather);
        CP_COMMIT();
    }

    // epilogue: optional RoPE, store fp32
    const int gr_ = lane >> 2, gc = (lane & 3) * 2;
#pragma unroll
    for (int mt = 0; mt < 4; mt++) {
        int r0 = brow + wm * 64 + mt * 16 + gr_;
#pragma unroll
        for (int nt = 0; nt < 4; nt++) {
            int col = bcol + wn * 32 + nt * 8 + gc;
            float c0 = acc[mt][nt][0], c1 = acc[mt][nt][1];
            float c2 = acc[mt][nt][2], c3 = acc[mt][nt][3];
            if (rope) {
                int f = (col & 63) >> 1;
                int l0 = r0 & lmask;
                float cc = cosT[l0 * 32 + f], ss = sinT[l0 * 32 + f];
                float t0 = c0 * cc - c1 * ss, t1 = c0 * ss + c1 * cc;
                c0 = t0; c1 = t1;
                int l1 = (r0 + 8) & lmask;
                cc = cosT[l1 * 32 + f]; ss = sinT[l1 * 32 + f];
                t0 = c2 * cc - c3 * ss; t1 = c2 * ss + c3 * cc;
                c2 = t0; c3 = t1;
            }
            *(float2*)(C + (size_t)r0 * N + col)       = make_float2(c0, c1);
            *(float2*)(C + (size_t)(r0 + 8) * N + col) = make_float2(c2, c3);
        }
    }
}

// fused Q/K/V projection GEMM: grid (8, 136)
__global__ __launch_bounds__(256, 2)
void qkv_gemm(const __half* __restrict__ xh, const __half* __restrict__ xl,
              const __half* __restrict__ Wq, const __half* __restrict__ Wk,
              const __half* __restrict__ Wv,
              float* __restrict__ Q, float* __restrict__ KF, float* __restrict__ VF,
              const float* __restrict__ cosT, const float* __restrict__ sinT)
{
    extern __shared__ __align__(128) char smem[];
    const int y = blockIdx.y;
    const int bcol = blockIdx.x * 128;

    const __half* Bh;
    float* C;
    int brow, lmask;
    bool rope, gather;
    if (y < 128)      { Bh = Wq; C = Q;  brow = y * 128;         rope = true;  gather = false; lmask = L_SEQ - 1; }
    else if (y < 132) { Bh = Wk; C = KF; brow = (y - 128) * 128; rope = true;  gather = true;  lmask = 127; }
    else              { Bh = Wv; C = VF; brow = (y - 132) * 128; rope = false; gather = true;  lmask = 0; }

    hm_body(xh, xl, Bh, C, brow, bcol, DIM, DIM, cosT, sinT, lmask, rope, gather, smem);
}

// output GEMM: out = AT @ Wo^T
__global__ __launch_bounds__(256, 2)
void o_gemm(const __half* __restrict__ Ah, const __half* __restrict__ Al,
            const __half* __restrict__ Bh, float* __restrict__ C)
{
    extern __shared__ __align__(128) char smem[];
    hm_body(Ah, Al, Bh, C, blockIdx.y * 128, blockIdx.x * 128, DIM, DIM,
            nullptr, nullptr, 0, false, false, smem);
}

// ================= projection: Kp[b,h,p,d] = sum_{l<=p} kpm[p,l]*KF[b,l,h*64+d] =================
// grid (64, 2): x = bh, y = phase (0=K, 1=V)
__global__ __launch_bounds__(256)
void proj_kernel(const float* __restrict__ Kf, const float* __restrict__ Vf,
                 const float* __restrict__ kpm, const float* __restrict__ vpm,
                 float* __restrict__ Kp, float* __restrict__ Vp)
{
    __shared__ float s[PDIM][HDIM + 4];
    const int bh = blockIdx.x;
    const int b = bh >> 4, h = bh & 15;
    const int tid = threadIdx.x;
    const int p = tid & 127;
    const int half = tid >> 7;
    const int phase = blockIdx.y;

    const float* src = phase == 0 ? Kf : Vf;
    const float* pm  = phase == 0 ? kpm : vpm;
    float* dst_base  = phase == 0 ? Kp : Vp;

    for (int i = tid; i < PDIM * (HDIM / 4); i += 256) {
        int l = i >> 4, c4 = (i & 15) * 4;
        float4 v = *(const float4*)(src + ((size_t)(b * 128 + l)) * DIM + h * HDIM + c4);
        s[l][c4] = v.x; s[l][c4 + 1] = v.y; s[l][c4 + 2] = v.z; s[l][c4 + 3] = v.w;
    }
    __syncthreads();

    float4 acc[8];
#pragma unroll
    for (int j = 0; j < 8; j++) acc[j] = make_float4(0.f, 0.f, 0.f, 0.f);

    for (int lc = 0; lc <= p; lc++) {
        float wv = pm[(size_t)p * 4096 + lc];
#pragma unroll
        for (int j = 0; j < 8; j++) {
            float4 kv = *(const float4*)&s[lc][half * 32 + j * 4];
            acc[j].x += wv * kv.x; acc[j].y += wv * kv.y;
            acc[j].z += wv * kv.z; acc[j].w += wv * kv.w;
        }
    }
    float* dst = dst_base + ((size_t)bh * PDIM + p) * HDIM + half * 32;
#pragma unroll
    for (int j = 0; j < 8; j++) *(float4*)(dst + j * 4) = acc[j];
}

// ================= attention (verified math, fp16 hi/lo output) =================
__global__ __launch_bounds__(256, 1)
void attn_kernel(const float* __restrict__ Q, const float* __restrict__ Kp,
                 const float* __restrict__ Vp,
                 __half* __restrict__ Oh, __half* __restrict__ Ol)
{
    __shared__ float s[PDIM][HDIM + 4];
    const int bid = blockIdx.x;
    const int ltile = bid & 15;
    const int bh = bid >> 4;
    const int b = bh >> 4;
    const int h = bh & 15;
    const int tid = threadIdx.x;
    const int l = ltile * 256 + tid;
    const size_t qbase = ((size_t)(b * L_SEQ + l)) * DIM + h * HDIM;

    for (int i = tid; i < PDIM * (HDIM / 4); i += 256) {
        int p = i >> 4, c4 = (i & 15) * 4;
        float4 v = *(const float4*)(Kp + ((size_t)bh * PDIM + p) * HDIM + c4);
        s[p][c4] = v.x; s[p][c4 + 1] = v.y; s[p][c4 + 2] = v.z; s[p][c4 + 3] = v.w;
    }
    __syncthreads();

    float w[PDIM];
#pragma unroll
    for (int p = 0; p < PDIM; p++) w[p] = 0.f;

    for (int d4 = 0; d4 < HDIM / 4; d4++) {
        float4 q4 = *(const float4*)(Q + qbase + d4 * 4);
#pragma unroll
        for (int p = 0; p < PDIM; p++) {
            float4 k4 = *(const float4*)&s[p][d4 * 4];
            w[p] += q4.x * k4.x + q4.y * k4.y + q4.z * k4.z + q4.w * k4.w;
        }
    }

    float m = -1e30f;
#pragma unroll
    for (int p = 0; p < PDIM; p++) {
        w[p] = (p <= l) ? w[p] * 0.125f : -1e30f;
        m = fmaxf(m, w[p]);
    }
    float Z = 0.f;
#pragma unroll
    for (int p = 0; p < PDIM; p++) {
        float e = __expf(w[p] - m);
        w[p] = e;
        Z += e;
    }
    float inv = 1.0f / Z;
#pragma unroll
    for (int p = 0; p < PDIM; p++) w[p] *= inv;

    __syncthreads();
    for (int i = tid; i < PDIM * (HDIM / 4); i += 256) {
        int p = i >> 4, c4 = (i & 15) * 4;
        float4 v = *(const float4*)(Vp + ((size_t)bh * PDIM + p) * HDIM + c4);
        s[p][c4] = v.x; s[p][c4 + 1] = v.y; s[p][c4 + 2] = v.z; s[p][c4 + 3] = v.w;
    }
    __syncthreads();

    for (int d4 = 0; d4 < HDIM / 4; d4++) {
        float4 o = make_float4(0.f, 0.f, 0.f, 0.f);
#pragma unroll
        for (int p = 0; p < PDIM; p++) {
            float4 v4 = *(const float4*)&s[p][d4 * 4];
            o.x += w[p] * v4.x; o.y += w[p] * v4.y;
            o.z += w[p] * v4.z; o.w += w[p] * v4.w;
        }
        __half h0 = __float2half_rn(o.x), h1 = __float2half_rn(o.y);
        __half h2 = __float2half_rn(o.z), h3 = __float2half_rn(o.w);
        __half e0 = __float2half_rn(o.x - __half2float(h0));
        __half e1 = __float2half_rn(o.y - __half2float(h1));
        __half e2 = __float2half_rn(o.z - __half2float(h2));
        __half e3 = __float2half_rn(o.w - __half2float(h3));
        *(uint2*)(Oh + qbase + d4 * 4) = make_uint2(pkhf(h0, h1), pkhf(h2, h3));
        *(uint2*)(Ol + qbase + d4 * 4) = make_uint2(pkhf(e0, e1), pkhf(e2, e3));
    }
}

// ================= launch =================
extern "C" void kernel_launch(void* const* d_in, const int* in_sizes, int n_in,
                              void* d_out, int out_size)
{
    const float* x   = (const float*)d_in[0];
    const float* fc  = (const float*)d_in[1];
    const float* fs  = (const float*)d_in[2];
    const float* Wq  = (const float*)d_in[3];
    const float* Wk  = (const float*)d_in[4];
    const float* Wv  = (const float*)d_in[5];
    const float* Wo  = (const float*)d_in[6];
    const float* kpm = (const float*)d_in[7];
    const float* vpm = (const float*)d_in[8];
    float* out = (float*)d_out;

    static bool inited = false;
    static __half *pxh, *pxl, *pWf[4], *pATh, *pATl;
    static float *pQ, *pKF, *pVF, *pKp, *pVp;
    if (!inited) {
        cudaGetSymbolAddress((void**)&pxh,  g_xh);
        cudaGetSymbolAddress((void**)&pxl,  g_xl);
        __half* base_w; cudaGetSymbolAddress((void**)&base_w, g_Wf);
        for (int i = 0; i < 4; i++) pWf[i] = base_w + (size_t)i * DIM * DIM;
        cudaGetSymbolAddress((void**)&pATh, g_ATh);
        cudaGetSymbolAddress((void**)&pATl, g_ATl);
        cudaGetSymbolAddress((void**)&pQ,  g_Q);
        cudaGetSymbolAddress((void**)&pKF, g_KF);
        cudaGetSymbolAddress((void**)&pVF, g_VF);
        cudaGetSymbolAddress((void**)&pKp, g_Kp);
        cudaGetSymbolAddress((void**)&pVp, g_Vp);
        cudaFuncSetAttribute(qkv_gemm, cudaFuncAttributeMaxDynamicSharedMemorySize, HM_SMEM);
        cudaFuncSetAttribute(o_gemm,   cudaFuncAttributeMaxDynamicSharedMemorySize, HM_SMEM);
        inited = true;
    }

    const int Mq = BATCH * L_SEQ;                    // 16384
    const int n4x = (int)((size_t)Mq * DIM / 4);
    const int n4w = DIM * DIM / 4;

    split_fp16<<<n4x / 256, 256>>>((const float4*)x, (uint2*)pxh, (uint2*)pxl, n4x);
    split_fp16_w<<<dim3(n4w / 256, 4), 256>>>((const float4*)Wq, (const float4*)Wk,
                                              (const float4*)Wv, (const float4*)Wo, n4w);

    // fused Q + K(first-128) + V(first-128) projection GEMMs (one launch)
    qkv_gemm<<<dim3(DIM / 128, Mq / 128 + 8), 256, HM_SMEM>>>(
        pxh, pxl, pWf[0], pWf[1], pWf[2], pQ, pKF, pVF, fc, fs);
    // causal low-rank projections (K and V in parallel blocks)
    proj_kernel<<<dim3(BATCH * NHEAD, 2), 256>>>(pKF, pVF, kpm, vpm, pKp, pVp);
    // attention -> fp16 hi/lo
    attn_kernel<<<BATCH * NHEAD * (L_SEQ / 256), 256>>>(pQ, pKp, pVp, pATh, pATl);
    // out = attn @ Wo^T
    o_gemm<<<dim3(DIM / 128, Mq / 128), 256, HM_SMEM>>>(pATh, pATl, pWf[3], out);
}

// round 8
// speedup vs baseline: 1.9129x; 1.2538x over previous
#include <cuda_runtime.h>
#include <cuda_fp16.h>
#include <cstdint>

#define L_SEQ 4096
#define DIM   1024
#define NHEAD 16
#define HDIM  64
#define PDIM  128
#define BATCH 4

// ================= scratch (device globals; no allocation allowed) =================
__device__ __half g_xh [(size_t)BATCH * L_SEQ * DIM];
__device__ __half g_Wf[4][DIM * DIM];                 // q,k,v,o fp16
__device__ float g_Q [(size_t)BATCH * L_SEQ * DIM];
__device__ float g_KF[BATCH * 128 * DIM];
__device__ float g_VF[BATCH * 128 * DIM];
__device__ float g_Kp[BATCH * NHEAD * PDIM * HDIM];
__device__ float g_Vp[BATCH * NHEAD * PDIM * HDIM];
__device__ __half g_AT[(size_t)BATCH * L_SEQ * DIM];

// ================= helpers =================
__device__ __forceinline__ uint32_t smem_u32(const void* p) {
    uint32_t a;
    asm("{ .reg .u64 t; cvta.to.shared.u64 t, %1; cvt.u32.u64 %0, t; }" : "=r"(a) : "l"(p));
    return a;
}
__device__ __forceinline__ uint32_t pkhf(__half a, __half b) {
    return (uint32_t)__half_as_ushort(a) | ((uint32_t)__half_as_ushort(b) << 16);
}

#define CP_ASYNC16(d, g) asm volatile("cp.async.cg.shared.global [%0], [%1], 16;\n" :: "r"(d), "l"(g) : "memory")
#define CP_COMMIT()      asm volatile("cp.async.commit_group;\n" ::: "memory")
#define CP_WAIT(n)       asm volatile("cp.async.wait_group %0;\n" :: "n"(n) : "memory")

__device__ __forceinline__ void ldsm_x4(uint32_t* r, uint32_t addr) {
    asm volatile("ldmatrix.sync.aligned.m8n8.x4.shared.b16 {%0,%1,%2,%3}, [%4];"
        : "=r"(r[0]), "=r"(r[1]), "=r"(r[2]), "=r"(r[3]) : "r"(addr));
}
__device__ __forceinline__ void mma16816(float* c, const uint32_t* a, const uint32_t* b) {
    asm volatile("mma.sync.aligned.m16n8k16.row.col.f32.f16.f16.f32 "
        "{%0,%1,%2,%3}, {%4,%5,%6,%7}, {%8,%9}, {%0,%1,%2,%3};"
        : "+f"(c[0]), "+f"(c[1]), "+f"(c[2]), "+f"(c[3])
        : "r"(a[0]), "r"(a[1]), "r"(a[2]), "r"(a[3]), "r"(b[0]), "r"(b[1]));
}

// ================= fp16 truncation kernels =================
__global__ void trunc_fp16(const float4* __restrict__ src, uint2* __restrict__ dst, int n4)
{
    int i = blockIdx.x * blockDim.x + threadIdx.x;
    if (i >= n4) return;
    float4 v = src[i];
    dst[i] = make_uint2(
        pkhf(__float2half_rn(v.x), __float2half_rn(v.y)),
        pkhf(__float2half_rn(v.z), __float2half_rn(v.w)));
}

__global__ void trunc_fp16_w(const float4* __restrict__ Wq, const float4* __restrict__ Wk,
                             const float4* __restrict__ Wv, const float4* __restrict__ Wo,
                             int n4)
{
    int i = blockIdx.x * blockDim.x + threadIdx.x;
    if (i >= n4) return;
    int w = blockIdx.y;
    const float4* src = (w == 0) ? Wq : (w == 1) ? Wk : (w == 2) ? Wv : Wo;
    float4 v = src[i];
    ((uint2*)g_Wf[w])[i] = make_uint2(
        pkhf(__float2half_rn(v.x), __float2half_rn(v.y)),
        pkhf(__float2half_rn(v.z), __float2half_rn(v.w)));
}

// ================= HMMA fp16 GEMM: C[M,N] = A[M,K] @ B[N,K]^T =================
// CTA tile 128x128, BK=32. 8 warps: wm = wid&1 (2x M64), wn = wid>>1 (4x N32).
// smem tiles 128 rows x 64B, XOR swizzle on 16B chunks: c ^= (row>>1)&3.
constexpr int TILE_BYTES  = 128 * 64;          // 8 KB
constexpr int STAGE_BYTES = 2 * TILE_BYTES;    // A, B
constexpr int HM_SMEM     = 2 * STAGE_BYTES;   // 32 KB
constexpr int OFF_B = TILE_BYTES;

__device__ __forceinline__ uint32_t a_addr(uint32_t tb, int row0, int kk, int lane) {
    int row = row0 + (lane & 15);
    int c = (2 * kk + (lane >> 4)) ^ ((row >> 1) & 3);
    return tb + row * 64 + c * 16;
}
__device__ __forceinline__ uint32_t b_addr(uint32_t tb, int n0, int kk, int lane) {
    int g = lane >> 3, lr = lane & 7;
    int n = n0 + lr + (g >> 1) * 8;
    int c = (2 * kk + (g & 1)) ^ ((n >> 1) & 3);
    return tb + n * 64 + c * 16;
}

__device__ __forceinline__ void hm_load(uint32_t stb,
    const __half* A, const __half* B,
    int brow, int bcol, int kofs, int K, int tid, bool gather)
{
#pragma unroll
    for (int t = 0; t < 2; t++) {
        const __half* src = (t == 0) ? A : B;
        int r0 = (t == 0) ? brow : bcol;
#pragma unroll
        for (int i = 0; i < 2; i++) {
            int id = tid + i * 256;          // 0..511
            int row = id >> 2, c = id & 3;
            int gr = r0 + row;
            if (gather && t == 0) gr = (gr >> 7) * L_SEQ + (gr & 127);
            const void* g = src + (size_t)gr * K + kofs + c * 8;
            uint32_t d = stb + t * TILE_BYTES + row * 64 + ((c ^ ((row >> 1) & 3)) * 16);
            CP_ASYNC16(d, g);
        }
    }
}

// shared GEMM body; rope/gather are CTA-uniform runtime flags
__device__ __forceinline__ void hm_body(
    const __half* A, const __half* B,
    float* C, int brow, int bcol, int K, int N,
    const float* cosT, const float* sinT, int lmask, bool rope, bool gather,
    char* smem)
{
    uint32_t sb = smem_u32(smem);
    const int tid = threadIdx.x;
    const int lane = tid & 31;
    const int wid = tid >> 5;
    const int wm = wid & 1, wn = wid >> 1;

    float acc[4][4][4];
#pragma unroll
    for (int a = 0; a < 4; a++)
#pragma unroll
        for (int b = 0; b < 4; b++)
#pragma unroll
            for (int c = 0; c < 4; c++) acc[a][b][c] = 0.f;

    const int NIT = K / 32;    // 32
    hm_load(sb, A, B, brow, bcol, 0, K, tid, gather);
    CP_COMMIT();
    hm_load(sb + STAGE_BYTES, A, B, brow, bcol, 32, K, tid, gather);
    CP_COMMIT();

    for (int it = 0; it < NIT; it++) {
        int s = it & 1;
        CP_WAIT(1);
        __syncthreads();
        uint32_t stb = sb + s * STAGE_BYTES;
#pragma unroll
        for (int kk = 0; kk < 2; kk++) {
            uint32_t af[16], bf[8];
#pragma unroll
            for (int mt = 0; mt < 4; mt++)
                ldsm_x4(af + mt * 4, a_addr(stb, wm * 64 + mt * 16, kk, lane));
#pragma unroll
            for (int np = 0; np < 2; np++)
                ldsm_x4(bf + np * 4, b_addr(stb + OFF_B, wn * 32 + np * 16, kk, lane));
#pragma unroll
            for (int mt = 0; mt < 4; mt++)
#pragma unroll
                for (int nt = 0; nt < 4; nt++)
                    mma16816(acc[mt][nt], af + mt * 4, bf + (nt >> 1) * 4 + (nt & 1) * 2);
        }
        __syncthreads();
        if (it + 2 < NIT)
            hm_load(sb + s * STAGE_BYTES, A, B, brow, bcol, (it + 2) * 32, K, tid, gather);
        CP_COMMIT();
    }

    // epilogue: optional RoPE, store fp32
    const int gr_ = lane >> 2, gc = (lane & 3) * 2;
#pragma unroll
    for (int mt = 0; mt < 4; mt++) {
        int r0 = brow + wm * 64 + mt * 16 + gr_;
#pragma unroll
        for (int nt = 0; nt < 4; nt++) {
            int col = bcol + wn * 32 + nt * 8 + gc;
            float c0 = acc[mt][nt][0], c1 = acc[mt][nt][1];
            float c2 = acc[mt][nt][2], c3 = acc[mt][nt][3];
            if (rope) {
                int f = (col & 63) >> 1;
                int l0 = r0 & lmask;
                float cc = cosT[l0 * 32 + f], ss = sinT[l0 * 32 + f];
                float t0 = c0 * cc - c1 * ss, t1 = c0 * ss + c1 * cc;
                c0 = t0; c1 = t1;
                int l1 = (r0 + 8) & lmask;
                cc = cosT[l1 * 32 + f]; ss = sinT[l1 * 32 + f];
                t0 = c2 * cc - c3 * ss; t1 = c2 * ss + c3 * cc;
                c2 = t0; c3 = t1;
            }
            *(float2*)(C + (size_t)r0 * N + col)       = make_float2(c0, c1);
            *(float2*)(C + (size_t)(r0 + 8) * N + col) = make_float2(c2, c3);
        }
    }
}

// fused Q/K/V projection GEMM: grid (8, 136)
__global__ __launch_bounds__(256, 2)
void qkv_gemm(const __half* __restrict__ xh,
              const __half* __restrict__ Wq, const __half* __restrict__ Wk,
              const __half* __restrict__ Wv,
              float* __restrict__ Q, float* __restrict__ KF, float* __restrict__ VF,
              const float* __restrict__ cosT, const float* __restrict__ sinT)
{
    extern __shared__ __align__(128) char smem[];
    const int y = blockIdx.y;
    const int bcol = blockIdx.x * 128;

    const __half* B;
    float* C;
    int brow, lmask;
    bool rope, gather;
    if (y < 128)      { B = Wq; C = Q;  brow = y * 128;         rope = true;  gather = false; lmask = L_SEQ - 1; }
    else if (y < 132) { B = Wk; C = KF; brow = (y - 128) * 128; rope = true;  gather = true;  lmask = 127; }
    else              { B = Wv; C = VF; brow = (y - 132) * 128; rope = false; gather = true;  lmask = 0; }

    hm_body(xh, B, C, brow, bcol, DIM, DIM, cosT, sinT, lmask, rope, gather, smem);
}

// output GEMM: out = AT @ Wo^T
__global__ __launch_bounds__(256, 2)
void o_gemm(const __half* __restrict__ A, const __half* __restrict__ B, float* __restrict__ C)
{
    extern __shared__ __align__(128) char smem[];
    hm_body(A, B, C, blockIdx.y * 128, blockIdx.x * 128, DIM, DIM,
            nullptr, nullptr, 0, false, false, smem);
}

// ================= projection: Kp[b,h,p,d] = sum_{l<=p} kpm[p,l]*KF[b,l,h*64+d] =================
// grid (64, 2): x = bh, y = phase (0=K, 1=V)
__global__ __launch_bounds__(256)
void proj_kernel(const float* __restrict__ Kf, const float* __restrict__ Vf,
                 const float* __restrict__ kpm, const float* __restrict__ vpm,
                 float* __restrict__ Kp, float* __restrict__ Vp)
{
    __shared__ float s[PDIM][HDIM + 4];
    const int bh = blockIdx.x;
    const int b = bh >> 4, h = bh & 15;
    const int tid = threadIdx.x;
    const int p = tid & 127;
    const int half = tid >> 7;
    const int phase = blockIdx.y;

    const float* src = phase == 0 ? Kf : Vf;
    const float* pm  = phase == 0 ? kpm : vpm;
    float* dst_base  = phase == 0 ? Kp : Vp;

    for (int i = tid; i < PDIM * (HDIM / 4); i += 256) {
        int l = i >> 4, c4 = (i & 15) * 4;
        float4 v = *(const float4*)(src + ((size_t)(b * 128 + l)) * DIM + h * HDIM + c4);
        s[l][c4] = v.x; s[l][c4 + 1] = v.y; s[l][c4 + 2] = v.z; s[l][c4 + 3] = v.w;
    }
    __syncthreads();

    float4 acc[8];
#pragma unroll
    for (int j = 0; j < 8; j++) acc[j] = make_float4(0.f, 0.f, 0.f, 0.f);

    for (int lc = 0; lc <= p; lc++) {
        float wv = pm[(size_t)p * 4096 + lc];
#pragma unroll
        for (int j = 0; j < 8; j++) {
            float4 kv = *(const float4*)&s[lc][half * 32 + j * 4];
            acc[j].x += wv * kv.x; acc[j].y += wv * kv.y;
            acc[j].z += wv * kv.z; acc[j].w += wv * kv.w;
        }
    }
    float* dst = dst_base + ((size_t)bh * PDIM + p) * HDIM + half * 32;
#pragma unroll
    for (int j = 0; j < 8; j++) *(float4*)(dst + j * 4) = acc[j];
}

// ================= attention (verified math, fp16 output) =================
__global__ __launch_bounds__(256, 1)
void attn_kernel(const float* __restrict__ Q, const float* __restrict__ Kp,
                 const float* __restrict__ Vp, __half* __restrict__ O)
{
    __shared__ float s[PDIM][HDIM + 4];
    const int bid = blockIdx.x;
    const int ltile = bid & 15;
    const int bh = bid >> 4;
    const int b = bh >> 4;
    const int h = bh & 15;
    const int tid = threadIdx.x;
    const int l = ltile * 256 + tid;
    const size_t qbase = ((size_t)(b * L_SEQ + l)) * DIM + h * HDIM;

    for (int i = tid; i < PDIM * (HDIM / 4); i += 256) {
        int p = i >> 4, c4 = (i & 15) * 4;
        float4 v = *(const float4*)(Kp + ((size_t)bh * PDIM + p) * HDIM + c4);
        s[p][c4] = v.x; s[p][c4 + 1] = v.y; s[p][c4 + 2] = v.z; s[p][c4 + 3] = v.w;
    }
    __syncthreads();

    float w[PDIM];
#pragma unroll
    for (int p = 0; p < PDIM; p++) w[p] = 0.f;

    for (int d4 = 0; d4 < HDIM / 4; d4++) {
        float4 q4 = *(const float4*)(Q + qbase + d4 * 4);
#pragma unroll
        for (int p = 0; p < PDIM; p++) {
            float4 k4 = *(const float4*)&s[p][d4 * 4];
            w[p] += q4.x * k4.x + q4.y * k4.y + q4.z * k4.z + q4.w * k4.w;
        }
    }

    float m = -1e30f;
#pragma unroll
    for (int p = 0; p < PDIM; p++) {
        w[p] = (p <= l) ? w[p] * 0.125f : -1e30f;
        m = fmaxf(m, w[p]);
    }
    float Z = 0.f;
#pragma unroll
    for (int p = 0; p < PDIM; p++) {
        float e = __expf(w[p] - m);
        w[p] = e;
        Z += e;
    }
    float inv = 1.0f / Z;
#pragma unroll
    for (int p = 0; p < PDIM; p++) w[p] *= inv;

    __syncthreads();
    for (int i = tid; i < PDIM * (HDIM / 4); i += 256) {
        int p = i >> 4, c4 = (i & 15) * 4;
        float4 v = *(const float4*)(Vp + ((size_t)bh * PDIM + p) * HDIM + c4);
        s[p][c4] = v.x; s[p][c4 + 1] = v.y; s[p][c4 + 2] = v.z; s[p][c4 + 3] = v.w;
    }
    __syncthreads();

    for (int d4 = 0; d4 < HDIM / 4; d4++) {
        float4 o = make_float4(0.f, 0.f, 0.f, 0.f);
#pragma unroll
        for (int p = 0; p < PDIM; p++) {
            float4 v4 = *(const float4*)&s[p][d4 * 4];
            o.x += w[p] * v4.x; o.y += w[p] * v4.y;
            o.z += w[p] * v4.z; o.w += w[p] * v4.w;
        }
        *(uint2*)(O + qbase + d4 * 4) = make_uint2(
            pkhf(__float2half_rn(o.x), __float2half_rn(o.y)),
            pkhf(__float2half_rn(o.z), __float2half_rn(o.w)));
    }
}

// ================= launch =================
extern "C" void kernel_launch(void* const* d_in, const int* in_sizes, int n_in,
                              void* d_out, int out_size)
{
    const float* x   = (const float*)d_in[0];
    const float* fc  = (const float*)d_in[1];
    const float* fs  = (const float*)d_in[2];
    const float* Wq  = (const float*)d_in[3];
    const float* Wk  = (const float*)d_in[4];
    const float* Wv  = (const float*)d_in[5];
    const float* Wo  = (const float*)d_in[6];
    const float* kpm = (const float*)d_in[7];
    const float* vpm = (const float*)d_in[8];
    float* out = (float*)d_out;

    static bool inited = false;
    static __half *pxh, *pWf[4], *pAT;
    static float *pQ, *pKF, *pVF, *pKp, *pVp;
    if (!inited) {
        cudaGetSymbolAddress((void**)&pxh, g_xh);
        __half* base_w; cudaGetSymbolAddress((void**)&base_w, g_Wf);
        for (int i = 0; i < 4; i++) pWf[i] = base_w + (size_t)i * DIM * DIM;
        cudaGetSymbolAddress((void**)&pAT, g_AT);
        cudaGetSymbolAddress((void**)&pQ,  g_Q);
        cudaGetSymbolAddress((void**)&pKF, g_KF);
        cudaGetSymbolAddress((void**)&pVF, g_VF);
        cudaGetSymbolAddress((void**)&pKp, g_Kp);
        cudaGetSymbolAddress((void**)&pVp, g_Vp);
        cudaFuncSetAttribute(qkv_gemm, cudaFuncAttributeMaxDynamicSharedMemorySize, HM_SMEM);
        cudaFuncSetAttribute(o_gemm,   cudaFuncAttributeMaxDynamicSharedMemorySize, HM_SMEM);
        inited = true;
    }

    const int Mq = BATCH * L_SEQ;                    // 16384
    const int n4x = (int)((size_t)Mq * DIM / 4);
    const int n4w = DIM * DIM / 4;

    trunc_fp16<<<n4x / 256, 256>>>((const float4*)x, (uint2*)pxh, n4x);
    trunc_fp16_w<<<dim3(n4w / 256, 4), 256>>>((const float4*)Wq, (const float4*)Wk,
                                              (const float4*)Wv, (const float4*)Wo, n4w);

    // fused Q + K(first-128) + V(first-128) projection GEMMs (one launch)
    qkv_gemm<<<dim3(DIM / 128, Mq / 128 + 8), 256, HM_SMEM>>>(
        pxh, pWf[0], pWf[1], pWf[2], pQ, pKF, pVF, fc, fs);
    // causal low-rank projections (K and V in parallel blocks)
    proj_kernel<<<dim3(BATCH * NHEAD, 2), 256>>>(pKF, pVF, kpm, vpm, pKp, pVp);
    // attention -> fp16
    attn_kernel<<<BATCH * NHEAD * (L_SEQ / 256), 256>>>(pQ, pKp, pVp, pAT);
    // out = attn @ Wo^T
    o_gemm<<<dim3(DIM / 128, Mq / 128), 256, HM_SMEM>>>(pAT, pWf[3], out);
}